// round 10
// baseline (speedup 1.0000x reference)
#include <cuda_runtime.h>
#include <cuda_fp16.h>

#define FULL 0xFFFFFFFFu

constexpr int B  = 16;
constexpr int T  = 512;
constexpr int C  = 3;
constexpr int V  = 16;
constexpr int H  = 128;
constexpr int NC = 12;

constexpr int THREADS = 256;
constexpr int NBLK    = 444;            // 148 SMs * 3 blocks -> exactly one wave
constexpr int NTILES  = B * T;          // tile = one (b,t) row = 16 positions

// LIF1 closed-form thresholds (validated R6/R8)
constexpr float TH3  = 2.0f / 3.0f;
constexpr float TH2p = 4.0f / 7.0f;
constexpr float TH1p = 8.0f / 15.0f;

// smem layout (bytes)
constexpr int W2_PITCH  = 136;                        // halfs/row
constexpr int IND_PITCH = 72;                         // halfs/row
constexpr int IND_BYTES = H * IND_PITCH * 2;          // 18432
constexpr int OFF_W2   = 0;                           // 34816
constexpr int OFF_IND0 = H * W2_PITCH * 2;            // 34816
constexpr int OFF_IND1 = OFF_IND0 + IND_BYTES;        // 53248
constexpr int OFF_C2   = OFF_IND1 + IND_BYTES;        // 71680
constexpr int OFF_INV2 = OFF_C2 + H * 4;
constexpr int SM_BYTES = OFF_INV2 + H * 4;            // 72704 -> 3 blocks/SM (213KB/SM)

__device__ float    g_acc[B * H];   // zero-init; reset by last block each call
__device__ unsigned g_ctr;          // ticket; reset by last block each call

__device__ __forceinline__ unsigned smem_u32(const void* p) {
    unsigned r;
    asm("{ .reg .u64 t; cvta.to.shared.u64 t, %1; cvt.u32.u64 %0, t; }" : "=r"(r) : "l"(p));
    return r;
}
__device__ __forceinline__ void ldmA4(unsigned* a, unsigned addr) {
    asm volatile("ldmatrix.sync.aligned.m8n8.x4.shared.b16 {%0,%1,%2,%3}, [%4];"
                 : "=r"(a[0]), "=r"(a[1]), "=r"(a[2]), "=r"(a[3]) : "r"(addr));
}
__device__ __forceinline__ void ldmB4t(unsigned* r, unsigned addr) {
    asm volatile("ldmatrix.sync.aligned.m8n8.x4.trans.shared.b16 {%0,%1,%2,%3}, [%4];"
                 : "=r"(r[0]), "=r"(r[1]), "=r"(r[2]), "=r"(r[3]) : "r"(addr));
}
__device__ __forceinline__ void mma16816(float* d, const unsigned* a, unsigned b0, unsigned b1) {
    asm volatile("mma.sync.aligned.m16n8k16.row.col.f32.f16.f16.f32 "
                 "{%0,%1,%2,%3}, {%4,%5,%6,%7}, {%8,%9}, {%0,%1,%2,%3};"
                 : "+f"(d[0]), "+f"(d[1]), "+f"(d[2]), "+f"(d[3])
                 : "r"(a[0]), "r"(a[1]), "r"(a[2]), "r"(a[3]), "r"(b0), "r"(b1));
}

// branch-free LIF2 over 4 steps; returns spike count
__device__ __forceinline__ float lif2(float A, float Bb1, float Bb2, float Bb3, float cc) {
    float base = A + cc;
    float h2 = base + Bb3;
    float h3 = base + Bb2;
    float h4 = h2 + Bb1;

    float v = base * 0.5f;
    bool s = v >= 0.5f;
    int cnt = s;
    v = s ? 0.f : v;

    v = fmaf(h2 - v, 0.5f, v);
    s = v >= 0.5f; cnt += s; v = s ? 0.f : v;

    v = fmaf(h3 - v, 0.5f, v);
    s = v >= 0.5f; cnt += s; v = s ? 0.f : v;

    v = fmaf(h4 - v, 0.5f, v);
    cnt += (v >= 0.5f);
    return (float)cnt;
}

// load one tile's x row slice for this thread's 8 positions (warp-uniform broadcasts)
__device__ __forceinline__ void ldg_x(const float* __restrict__ xr, int ph, float4* xa) {
    const float4* xr4 = reinterpret_cast<const float4*>(xr);
    xa[0] = xr4[2 * ph + 0]; xa[1] = xr4[2 * ph + 1];     // x0: positions 8ph..8ph+7
    xa[2] = xr4[4 + 2 * ph]; xa[3] = xr4[5 + 2 * ph];     // x1
    xa[4] = xr4[8 + 2 * ph]; xa[5] = xr4[9 + 2 * ph];     // x2
}

// compute one-hot fp16 categories for 8 positions; 4x STS.128 into indicator row
__device__ __forceinline__ void build_store(const float4* xa, float w1a, float w1b, float w1c,
                                            float c1v, unsigned* indw, int ph) {
    const float* f = reinterpret_cast<const float*>(xa);
    unsigned pk0[8], pk1[8];
#pragma unroll
    for (int j = 0; j < 8; j++) {
        float h = fmaf(w1a, f[j], fmaf(w1b, f[8 + j], fmaf(w1c, f[16 + j], c1v)));
        bool s4 = h >= 1.0f;
        bool s3 = h >= TH3;
        bool s2 = h >= TH2p;
        bool s1 = h >= TH1p;
        pk0[j] = (s4 ? 0x3C00u : 0u) | ((s3 && !s4) ? 0x3C000000u : 0u);   // cat4|cat3
        pk1[j] = ((s2 && !s3) ? 0x3C00u : 0u) | ((s1 && !s2) ? 0x3C000000u : 0u); // cat2|cat1
    }
    int g0 = 2 * ph;
    *reinterpret_cast<uint4*>(indw + 8 * g0)     = make_uint4(pk0[0], pk0[1], pk0[2], pk0[3]);
    *reinterpret_cast<uint4*>(indw + 8 * g0 + 4) = make_uint4(pk1[0], pk1[1], pk1[2], pk1[3]);
    *reinterpret_cast<uint4*>(indw + 8 * g0 + 8)  = make_uint4(pk0[4], pk0[5], pk0[6], pk0[7]);
    *reinterpret_cast<uint4*>(indw + 8 * g0 + 12) = make_uint4(pk1[4], pk1[5], pk1[6], pk1[7]);
}

// one n-group-pair mma sweep for group g; accumulates spike counts
__device__ __forceinline__ void mma_g(int g, unsigned indbase, int lane,
                                      const unsigned (*aF)[4],
                                      float c2Lo, float c2Hi, float& cLo, float& cHi) {
    float d0[4] = {0.f, 0.f, 0.f, 0.f};     // n-tile s=0: (cat4, cat3)
    float d1[4] = {0.f, 0.f, 0.f, 0.f};     // n-tile s=1: (cat2, cat1)
#pragma unroll
    for (int j2 = 0; j2 < 4; j2++) {
        unsigned r[4], e[4];
        unsigned ad = indbase + (unsigned)((32 * j2 + lane) * IND_PITCH + 16 * g) * 2u;
        ldmB4t(r, ad);
        ldmB4t(e, ad + 16u);                // +8 half cols
        mma16816(d0, aF[2 * j2],     r[0], r[1]);
        mma16816(d0, aF[2 * j2 + 1], r[2], r[3]);
        mma16816(d1, aF[2 * j2],     e[0], e[1]);
        mma16816(d1, aF[2 * j2 + 1], e[2], e[3]);
    }
    cLo += lif2(d0[0], d1[1], d1[0], d0[1], c2Lo);
    cHi += lif2(d0[2], d1[3], d1[2], d0[3], c2Hi);
}

__global__ void __launch_bounds__(THREADS, 3)
snn_main(const float* __restrict__ x,
         const float* __restrict__ w1, const float* __restrict__ b1,
         const float* __restrict__ g1, const float* __restrict__ be1,
         const float* __restrict__ m1, const float* __restrict__ rv1,
         const float* __restrict__ w2, const float* __restrict__ b2,
         const float* __restrict__ g2, const float* __restrict__ be2,
         const float* __restrict__ m2, const float* __restrict__ rv2,
         const float* __restrict__ wc, const float* __restrict__ bc,
         float* __restrict__ out) {
    extern __shared__ __align__(16) unsigned char smraw[];
    __half* w2h   = reinterpret_cast<__half*>(smraw + OFF_W2);
    float*  c2s   = reinterpret_cast<float*>(smraw + OFF_C2);
    float*  inv2s = reinterpret_cast<float*>(smraw + OFF_INV2);

    const int tid  = threadIdx.x;
    const int warp = tid >> 5, lane = tid & 31;

    // ---- fold BN2; stage W2' fp16, output-channel-major rows (A operand) ----
    if (tid < H) {
        float inv2 = g2[tid] * rsqrtf(rv2[tid] + 1e-5f);
        inv2s[tid] = inv2;
        c2s[tid]   = (b2[tid] - m2[tid]) * inv2 + be2[tid];
    }
    __syncthreads();
    for (int i = tid; i < H * H; i += THREADS) {
        int p = i >> 7, o = i & 127;
        w2h[p * W2_PITCH + o] = __float2half_rn(w2[i] * inv2s[p]);
    }
    __syncthreads();

    // ---- stationary A fragments: warp w covers outchans 16w..16w+15 ----
    unsigned aF[8][4];
    {
        unsigned w2base = smem_u32(w2h);
        int r   = 16 * warp + (lane & 15);
        int ch8 = (lane >> 4) * 8;
#pragma unroll
        for (int kk = 0; kk < 8; kk++)
            ldmA4(aF[kk], w2base + (unsigned)((r * W2_PITCH) + kk * 16 + ch8) * 2u);
    }

    // ---- per-thread build params ----
    const int mych = tid & 127;
    const int ph   = tid >> 7;
    float w1a, w1b, w1c, c1v;
    {
        float inv1 = g1[mych] * rsqrtf(rv1[mych] + 1e-5f);
        w1a = w1[mych * 3 + 0] * inv1;
        w1b = w1[mych * 3 + 1] * inv1;
        w1c = w1[mych * 3 + 2] * inv1;
        c1v = (b1[mych] - m1[mych]) * inv1 + be1[mych];
    }
    const int q  = lane >> 2;
    const int pp = lane & 3;
    const float c2Lo = c2s[16 * warp + q];
    const float c2Hi = c2s[16 * warp + q + 8];

    unsigned  indbase[2] = { smem_u32(smraw + OFF_IND0), smem_u32(smraw + OFF_IND1) };
    unsigned* indw[2] = {
        reinterpret_cast<unsigned*>(smraw + OFF_IND0) + mych * (IND_PITCH / 2),
        reinterpret_cast<unsigned*>(smraw + OFF_IND1) + mych * (IND_PITCH / 2) };

    // ---- software-pipelined persistent tile loop ----
    int t0 = blockIdx.x;
    if (t0 < NTILES) {
        float4 xa[6];
        ldg_x(x + (size_t)t0 * (C * V), ph, xa);
        build_store(xa, w1a, w1b, w1c, c1v, indw[0], ph);
    }
    __syncthreads();

    int cur = 0;
    for (int t = t0; t < NTILES; t += NBLK, cur ^= 1) {
        const int bb  = t >> 9;
        const int nxt = t + NBLK;
        const bool has = nxt < NTILES;

        float4 xa[6];
        if (has) ldg_x(x + (size_t)nxt * (C * V), ph, xa);   // in flight under mma

        float cLo = 0.f, cHi = 0.f;
        mma_g(0, indbase[cur], lane, aF, c2Lo, c2Hi, cLo, cHi);
        mma_g(1, indbase[cur], lane, aF, c2Lo, c2Hi, cLo, cHi);

        if (has) build_store(xa, w1a, w1b, w1c, c1v, indw[cur ^ 1], ph);

        mma_g(2, indbase[cur], lane, aF, c2Lo, c2Hi, cLo, cHi);
        mma_g(3, indbase[cur], lane, aF, c2Lo, c2Hi, cLo, cHi);

        // reduce positions within quad, flush (exact integer-valued fp32)
        cLo += __shfl_xor_sync(FULL, cLo, 1); cLo += __shfl_xor_sync(FULL, cLo, 2);
        cHi += __shfl_xor_sync(FULL, cHi, 1); cHi += __shfl_xor_sync(FULL, cHi, 2);
        if (pp == 0) {
            atomicAdd(&g_acc[bb * H + 16 * warp + q], cLo);
            atomicAdd(&g_acc[bb * H + 16 * warp + q + 8], cHi);
        }
        __syncthreads();     // buf[cur^1] fully built + all reads of buf[cur] done
    }

    // ---- last-block epilogue: feat -> classifier, reset state ----
    __shared__ unsigned s_ticket;
    __threadfence();
    __syncthreads();
    if (tid == 0) s_ticket = atomicAdd(&g_ctr, 1u);
    __syncthreads();
    if (s_ticket == NBLK - 1) {
        __threadfence();
        float* feat = reinterpret_cast<float*>(smraw + OFF_IND0);
        for (int i = tid; i < B * H; i += THREADS) {
            float v = __ldcg(&g_acc[i]);
            feat[i] = v * (1.f / (4.f * (float)(T * V)));
            g_acc[i] = 0.f;
        }
        __syncthreads();
        if (tid < B * NC) {
            int b = tid / NC, n = tid % NC;
            float s = bc[n];
#pragma unroll 8
            for (int pch = 0; pch < H; pch++)
                s = fmaf(wc[n * H + pch], feat[b * H + pch], s);
            out[b * NC + n] = s;
        }
        if (tid == 0) atomicExch(&g_ctr, 0u);
    }
}

extern "C" void kernel_launch(void* const* d_in, const int* in_sizes, int n_in,
                              void* d_out, int out_size) {
    const float* x   = (const float*)d_in[0];
    const float* w1  = (const float*)d_in[1];
    const float* b1  = (const float*)d_in[2];
    const float* g1  = (const float*)d_in[3];
    const float* be1 = (const float*)d_in[4];
    const float* m1  = (const float*)d_in[5];
    const float* rv1 = (const float*)d_in[6];
    const float* w2  = (const float*)d_in[7];
    const float* b2  = (const float*)d_in[8];
    const float* g2  = (const float*)d_in[9];
    const float* be2 = (const float*)d_in[10];
    const float* m2  = (const float*)d_in[11];
    const float* rv2 = (const float*)d_in[12];
    const float* wc  = (const float*)d_in[13];
    const float* bc  = (const float*)d_in[14];

    cudaFuncSetAttribute(snn_main, cudaFuncAttributeMaxDynamicSharedMemorySize, SM_BYTES);

    snn_main<<<NBLK, THREADS, SM_BYTES>>>(x, w1, b1, g1, be1, m1, rv1,
                                          w2, b2, g2, be2, m2, rv2,
                                          wc, bc, (float*)d_out);
}

// round 12
// speedup vs baseline: 1.2192x; 1.2192x over previous
#include <cuda_runtime.h>
#include <cuda_fp16.h>

#define FULL 0xFFFFFFFFu

constexpr int B  = 16;
constexpr int T  = 512;
constexpr int C  = 3;
constexpr int V  = 16;
constexpr int H  = 128;
constexpr int NC = 12;

constexpr int THREADS   = 256;
constexpr int BLK_PER_B = 37;
constexpr int NBLK      = B * BLK_PER_B;      // 592 = 148 SMs * 4 blocks, one wave

// LIF1 closed-form thresholds (validated R6/R8/R9)
constexpr float TH3  = 2.0f / 3.0f;
constexpr float TH2p = 4.0f / 7.0f;
constexpr float TH1p = 8.0f / 15.0f;

// smem layout (bytes)
constexpr int W2_PITCH  = 136;                       // halfs/row
constexpr int IND_PITCH = 72;                        // halfs/row
constexpr int OFF_W2   = 0;                          // 34816
constexpr int OFF_IND  = H * W2_PITCH * 2;           // 34816
constexpr int OFF_C2   = OFF_IND + H * IND_PITCH * 2;  // 53248
constexpr int OFF_INV2 = OFF_C2 + H * 4;
constexpr int SM_BYTES = OFF_INV2 + H * 4;           // 54272 -> 4 blocks/SM

__device__ float    g_acc[B * H];   // zero-init; reset by last block each call
__device__ unsigned g_ctr;          // ticket; reset by last block each call

__device__ __forceinline__ unsigned smem_u32(const void* p) {
    unsigned r;
    asm("{ .reg .u64 t; cvta.to.shared.u64 t, %1; cvt.u32.u64 %0, t; }" : "=r"(r) : "l"(p));
    return r;
}
__device__ __forceinline__ void ldmA4(unsigned* a, unsigned addr) {
    asm volatile("ldmatrix.sync.aligned.m8n8.x4.shared.b16 {%0,%1,%2,%3}, [%4];"
                 : "=r"(a[0]), "=r"(a[1]), "=r"(a[2]), "=r"(a[3]) : "r"(addr));
}
__device__ __forceinline__ void ldmB4t(unsigned* r, unsigned addr) {
    asm volatile("ldmatrix.sync.aligned.m8n8.x4.trans.shared.b16 {%0,%1,%2,%3}, [%4];"
                 : "=r"(r[0]), "=r"(r[1]), "=r"(r[2]), "=r"(r[3]) : "r"(addr));
}
__device__ __forceinline__ void mma16816(float* d, const unsigned* a, unsigned b0, unsigned b1) {
    asm volatile("mma.sync.aligned.m16n8k16.row.col.f32.f16.f16.f32 "
                 "{%0,%1,%2,%3}, {%4,%5,%6,%7}, {%8,%9}, {%0,%1,%2,%3};"
                 : "+f"(d[0]), "+f"(d[1]), "+f"(d[2]), "+f"(d[3])
                 : "r"(a[0]), "r"(a[1]), "r"(a[2]), "r"(a[3]), "r"(b0), "r"(b1));
}

// branch-free LIF2 over 4 steps; returns spike count
__device__ __forceinline__ float lif2(float A, float Bb1, float Bb2, float Bb3, float cc) {
    float base = A + cc;
    float h2 = base + Bb3;
    float h3 = base + Bb2;
    float h4 = h2 + Bb1;

    float v = base * 0.5f;
    bool s = v >= 0.5f;
    int cnt = s;
    v = s ? 0.f : v;

    v = fmaf(h2 - v, 0.5f, v);
    s = v >= 0.5f; cnt += s; v = s ? 0.f : v;

    v = fmaf(h3 - v, 0.5f, v);
    s = v >= 0.5f; cnt += s; v = s ? 0.f : v;

    v = fmaf(h4 - v, 0.5f, v);
    cnt += (v >= 0.5f);
    return (float)cnt;
}

// one n-group-pair mma sweep for group g; accumulates spike counts across tiles
__device__ __forceinline__ void mma_g(int g, unsigned indbase, int lane,
                                      const unsigned (*aF)[4],
                                      float c2Lo, float c2Hi, float& cLo, float& cHi) {
    float d0[4] = {0.f, 0.f, 0.f, 0.f};     // n-tile s=0: (cat4, cat3)
    float d1[4] = {0.f, 0.f, 0.f, 0.f};     // n-tile s=1: (cat2, cat1)
#pragma unroll
    for (int j2 = 0; j2 < 4; j2++) {
        unsigned r[4], e[4];
        unsigned ad = indbase + (unsigned)((32 * j2 + lane) * IND_PITCH + 16 * g) * 2u;
        ldmB4t(r, ad);
        ldmB4t(e, ad + 16u);                // +8 half cols
        mma16816(d0, aF[2 * j2],     r[0], r[1]);
        mma16816(d0, aF[2 * j2 + 1], r[2], r[3]);
        mma16816(d1, aF[2 * j2],     e[0], e[1]);
        mma16816(d1, aF[2 * j2 + 1], e[2], e[3]);
    }
    cLo += lif2(d0[0], d1[1], d1[0], d0[1], c2Lo);
    cHi += lif2(d0[2], d1[3], d1[2], d0[3], c2Hi);
}

__global__ void __launch_bounds__(THREADS, 4)
snn_main(const float* __restrict__ x,
         const float* __restrict__ w1, const float* __restrict__ b1,
         const float* __restrict__ g1, const float* __restrict__ be1,
         const float* __restrict__ m1, const float* __restrict__ rv1,
         const float* __restrict__ w2, const float* __restrict__ b2,
         const float* __restrict__ g2, const float* __restrict__ be2,
         const float* __restrict__ m2, const float* __restrict__ rv2,
         const float* __restrict__ wc, const float* __restrict__ bc,
         float* __restrict__ out) {
    extern __shared__ __align__(16) unsigned char smraw[];
    __half* w2h   = reinterpret_cast<__half*>(smraw + OFF_W2);
    float*  c2s   = reinterpret_cast<float*>(smraw + OFF_C2);
    float*  inv2s = reinterpret_cast<float*>(smraw + OFF_INV2);

    const int tid  = threadIdx.x;
    const int warp = tid >> 5, lane = tid & 31;

    // ---- fold BN2; stage W2' fp16, output-channel-major rows (A operand) ----
    if (tid < H) {
        float inv2 = g2[tid] * rsqrtf(rv2[tid] + 1e-5f);
        inv2s[tid] = inv2;
        c2s[tid]   = (b2[tid] - m2[tid]) * inv2 + be2[tid];
    }
    __syncthreads();
    for (int i = tid; i < H * H; i += THREADS) {
        int p = i >> 7, o = i & 127;
        w2h[p * W2_PITCH + o] = __float2half_rn(w2[i] * inv2s[p]);
    }
    __syncthreads();

    // ---- stationary A fragments: warp w covers outchans 16w..16w+15 ----
    unsigned aF[8][4];
    {
        unsigned w2base = smem_u32(w2h);
        int r   = 16 * warp + (lane & 15);
        int ch8 = (lane >> 4) * 8;
#pragma unroll
        for (int kk = 0; kk < 8; kk++)
            ldmA4(aF[kk], w2base + (unsigned)((r * W2_PITCH) + kk * 16 + ch8) * 2u);
    }

    // ---- per-thread build params ----
    const int mych = tid & 127;
    const int ph   = tid >> 7;
    float w1a, w1b, w1c, c1v;
    {
        float inv1 = g1[mych] * rsqrtf(rv1[mych] + 1e-5f);
        w1a = w1[mych * 3 + 0] * inv1;
        w1b = w1[mych * 3 + 1] * inv1;
        w1c = w1[mych * 3 + 2] * inv1;
        c1v = (b1[mych] - m1[mych]) * inv1 + be1[mych];
    }
    const int q  = lane >> 2;
    const int pp = lane & 3;
    const float c2Lo = c2s[16 * warp + q];
    const float c2Hi = c2s[16 * warp + q + 8];

    const unsigned indbase = smem_u32(smraw + OFF_IND);
    unsigned* indw = reinterpret_cast<unsigned*>(smraw + OFF_IND) + mych * (IND_PITCH / 2);

    // ---- contiguous tile span: block = (batch bb, row span j of 37) ----
    const int bb = blockIdx.x / BLK_PER_B;
    const int j  = blockIdx.x % BLK_PER_B;
    const int r0 = (j * T) / BLK_PER_B;
    const int r1 = ((j + 1) * T) / BLK_PER_B;
    const float* xb = x + (size_t)bb * (T * C * V);

    float cLo = 0.f, cHi = 0.f;              // spike counts across ALL this block's tiles

    for (int r = r0; r < r1; r++) {
        const float4* xr4 = reinterpret_cast<const float4*>(xb + r * (C * V));

        __syncthreads();                     // prior tile's mma reads complete
        // build indicator in 2 chunks of 4 positions (low register pressure)
#pragma unroll
        for (int c = 0; c < 2; c++) {
            float4 v0 = xr4[2 * ph + c];     // x0, positions 8ph+4c..+3
            float4 v1 = xr4[4 + 2 * ph + c]; // x1
            float4 v2 = xr4[8 + 2 * ph + c]; // x2
            const float* f0 = reinterpret_cast<const float*>(&v0);
            const float* f1 = reinterpret_cast<const float*>(&v1);
            const float* f2 = reinterpret_cast<const float*>(&v2);
            unsigned pk0[4], pk1[4];
#pragma unroll
            for (int jj = 0; jj < 4; jj++) {
                float h = fmaf(w1a, f0[jj], fmaf(w1b, f1[jj], fmaf(w1c, f2[jj], c1v)));
                bool s4 = h >= 1.0f;
                bool s3 = h >= TH3;
                bool s2 = h >= TH2p;
                bool s1 = h >= TH1p;
                pk0[jj] = (s4 ? 0x3C00u : 0u) | ((s3 && !s4) ? 0x3C000000u : 0u);        // cat4|cat3
                pk1[jj] = ((s2 && !s3) ? 0x3C00u : 0u) | ((s1 && !s2) ? 0x3C000000u : 0u); // cat2|cat1
            }
            int g = 2 * ph + c;
            *reinterpret_cast<uint4*>(indw + 8 * g)     = make_uint4(pk0[0], pk0[1], pk0[2], pk0[3]);
            *reinterpret_cast<uint4*>(indw + 8 * g + 4) = make_uint4(pk1[0], pk1[1], pk1[2], pk1[3]);
        }
        __syncthreads();

        mma_g(0, indbase, lane, aF, c2Lo, c2Hi, cLo, cHi);
        mma_g(1, indbase, lane, aF, c2Lo, c2Hi, cLo, cHi);
        mma_g(2, indbase, lane, aF, c2Lo, c2Hi, cLo, cHi);
        mma_g(3, indbase, lane, aF, c2Lo, c2Hi, cLo, cHi);
    }

    // single flush: reduce positions within quad, one atomic set per block
    cLo += __shfl_xor_sync(FULL, cLo, 1); cLo += __shfl_xor_sync(FULL, cLo, 2);
    cHi += __shfl_xor_sync(FULL, cHi, 1); cHi += __shfl_xor_sync(FULL, cHi, 2);
    if (pp == 0) {                           // exact integer-valued fp32 adds
        atomicAdd(&g_acc[bb * H + 16 * warp + q], cLo);
        atomicAdd(&g_acc[bb * H + 16 * warp + q + 8], cHi);
    }

    // ---- last-block epilogue: feat -> classifier, reset state ----
    __shared__ unsigned s_ticket;
    __threadfence();
    __syncthreads();
    if (tid == 0) s_ticket = atomicAdd(&g_ctr, 1u);
    __syncthreads();
    if (s_ticket == NBLK - 1) {
        __threadfence();
        float* feat = reinterpret_cast<float*>(smraw + OFF_IND);
        for (int i = tid; i < B * H; i += THREADS) {
            float v = __ldcg(&g_acc[i]);
            feat[i] = v * (1.f / (4.f * (float)(T * V)));
            g_acc[i] = 0.f;
        }
        __syncthreads();
        if (tid < B * NC) {
            int b = tid / NC, n = tid % NC;
            float s = bc[n];
#pragma unroll 8
            for (int pch = 0; pch < H; pch++)
                s = fmaf(wc[n * H + pch], feat[b * H + pch], s);
            out[b * NC + n] = s;
        }
        if (tid == 0) atomicExch(&g_ctr, 0u);
    }
}

extern "C" void kernel_launch(void* const* d_in, const int* in_sizes, int n_in,
                              void* d_out, int out_size) {
    const float* x   = (const float*)d_in[0];
    const float* w1  = (const float*)d_in[1];
    const float* b1  = (const float*)d_in[2];
    const float* g1  = (const float*)d_in[3];
    const float* be1 = (const float*)d_in[4];
    const float* m1  = (const float*)d_in[5];
    const float* rv1 = (const float*)d_in[6];
    const float* w2  = (const float*)d_in[7];
    const float* b2  = (const float*)d_in[8];
    const float* g2  = (const float*)d_in[9];
    const float* be2 = (const float*)d_in[10];
    const float* m2  = (const float*)d_in[11];
    const float* rv2 = (const float*)d_in[12];
    const float* wc  = (const float*)d_in[13];
    const float* bc  = (const float*)d_in[14];

    cudaFuncSetAttribute(snn_main, cudaFuncAttributeMaxDynamicSharedMemorySize, SM_BYTES);

    snn_main<<<NBLK, THREADS, SM_BYTES>>>(x, w1, b1, g1, be1, m1, rv1,
                                          w2, b2, g2, be2, m2, rv2,
                                          wc, bc, (float*)d_out);
}

// round 14
// speedup vs baseline: 1.2197x; 1.0004x over previous
#include <cuda_runtime.h>
#include <cuda_fp16.h>

#define FULL 0xFFFFFFFFu

constexpr int B  = 16;
constexpr int T  = 512;
constexpr int C  = 3;
constexpr int V  = 16;
constexpr int H  = 128;
constexpr int NC = 12;

constexpr int THREADS   = 256;
constexpr int BLK_PER_B = 37;
constexpr int NBLK      = B * BLK_PER_B;      // 592 = 148 SMs * 4 blocks, one wave

// LIF1 closed-form thresholds (validated R6/R8/R9/R12)
constexpr float TH3  = 2.0f / 3.0f;
constexpr float TH2p = 4.0f / 7.0f;
constexpr float TH1p = 8.0f / 15.0f;

// smem layout (bytes)
constexpr int W2_PITCH  = 136;                       // halfs/row
constexpr int IND_PITCH = 72;                        // halfs/row
constexpr int OFF_W2   = 0;                          // 34816
constexpr int OFF_IND  = H * W2_PITCH * 2;           // 34816
constexpr int OFF_C2   = OFF_IND + H * IND_PITCH * 2;  // 53248
constexpr int OFF_INV2 = OFF_C2 + H * 4;
constexpr int SM_BYTES = OFF_INV2 + H * 4;           // 54272 -> 4 blocks/SM

__device__ float    g_acc[B * H];   // zero-init; reset by last block each call
__device__ unsigned g_ctr;          // ticket; reset by last block each call

__device__ __forceinline__ unsigned smem_u32(const void* p) {
    unsigned r;
    asm("{ .reg .u64 t; cvta.to.shared.u64 t, %1; cvt.u32.u64 %0, t; }" : "=r"(r) : "l"(p));
    return r;
}
__device__ __forceinline__ void ldmA4(unsigned* a, unsigned addr) {
    asm volatile("ldmatrix.sync.aligned.m8n8.x4.shared.b16 {%0,%1,%2,%3}, [%4];"
                 : "=r"(a[0]), "=r"(a[1]), "=r"(a[2]), "=r"(a[3]) : "r"(addr));
}
__device__ __forceinline__ void ldmB4t(unsigned* r, unsigned addr) {
    asm volatile("ldmatrix.sync.aligned.m8n8.x4.trans.shared.b16 {%0,%1,%2,%3}, [%4];"
                 : "=r"(r[0]), "=r"(r[1]), "=r"(r[2]), "=r"(r[3]) : "r"(addr));
}
__device__ __forceinline__ void mma16816(float* d, const unsigned* a, unsigned b0, unsigned b1) {
    asm volatile("mma.sync.aligned.m16n8k16.row.col.f32.f16.f16.f32 "
                 "{%0,%1,%2,%3}, {%4,%5,%6,%7}, {%8,%9}, {%0,%1,%2,%3};"
                 : "+f"(d[0]), "+f"(d[1]), "+f"(d[2]), "+f"(d[3])
                 : "r"(a[0]), "r"(a[1]), "r"(a[2]), "r"(a[3]), "r"(b0), "r"(b1));
}

// LIF2 with PRE-HALVED inputs (W2', c2 staged * 0.5): v_next = fma(v, 0.5, h_next/2).
// v stays true-scale; thresholds unchanged. Returns spike count (int).
__device__ __forceinline__ int lif2h(float Ah, float B1h, float B2h, float B3h, float c2h) {
    float baseh = Ah + c2h;           // = h1/2 = v1
    float h2h = baseh + B3h;
    float h3h = baseh + B2h;
    float h4h = h2h + B1h;

    float v = baseh;
    bool s = v >= 0.5f;
    int cnt = s;
    v = s ? 0.f : v;

    v = fmaf(v, 0.5f, h2h);
    s = v >= 0.5f; cnt += s; v = s ? 0.f : v;

    v = fmaf(v, 0.5f, h3h);
    s = v >= 0.5f; cnt += s; v = s ? 0.f : v;

    v = fmaf(v, 0.5f, h4h);
    cnt += (v >= 0.5f);
    return cnt;
}

// one n-group-pair mma sweep for group g; accumulates spike counts (int) across tiles
__device__ __forceinline__ void mma_g(int g, const unsigned* __restrict__ adb,
                                      const unsigned (*aF)[4],
                                      float c2Lo, float c2Hi, int& cLo, int& cHi) {
    float d0[4] = {0.f, 0.f, 0.f, 0.f};     // n-tile s=0: (cat4, cat3)
    float d1[4] = {0.f, 0.f, 0.f, 0.f};     // n-tile s=1: (cat2, cat1)
#pragma unroll
    for (int j2 = 0; j2 < 4; j2++) {
        unsigned r[4], e[4];
        unsigned ad = adb[j2] + (unsigned)(g * 32);   // hoisted base + imm offset
        ldmB4t(r, ad);
        ldmB4t(e, ad + 16u);                // +8 half cols
        mma16816(d0, aF[2 * j2],     r[0], r[1]);
        mma16816(d0, aF[2 * j2 + 1], r[2], r[3]);
        mma16816(d1, aF[2 * j2],     e[0], e[1]);
        mma16816(d1, aF[2 * j2 + 1], e[2], e[3]);
    }
    cLo += lif2h(d0[0], d1[1], d1[0], d0[1], c2Lo);
    cHi += lif2h(d0[2], d1[3], d1[2], d0[3], c2Hi);
}

__global__ void __launch_bounds__(THREADS, 4)
snn_main(const float* __restrict__ x,
         const float* __restrict__ w1, const float* __restrict__ b1,
         const float* __restrict__ g1, const float* __restrict__ be1,
         const float* __restrict__ m1, const float* __restrict__ rv1,
         const float* __restrict__ w2, const float* __restrict__ b2,
         const float* __restrict__ g2, const float* __restrict__ be2,
         const float* __restrict__ m2, const float* __restrict__ rv2,
         const float* __restrict__ wc, const float* __restrict__ bc,
         float* __restrict__ out) {
    extern __shared__ __align__(16) unsigned char smraw[];
    __half* w2h   = reinterpret_cast<__half*>(smraw + OFF_W2);
    float*  c2s   = reinterpret_cast<float*>(smraw + OFF_C2);
    float*  inv2s = reinterpret_cast<float*>(smraw + OFF_INV2);

    const int tid  = threadIdx.x;
    const int warp = tid >> 5, lane = tid & 31;

    // ---- fold BN2 AND the LIF 1/TAU=0.5 into W2'/c2 (pre-halved) ----
    if (tid < H) {
        float inv2 = g2[tid] * rsqrtf(rv2[tid] + 1e-5f);
        inv2s[tid] = inv2;
        c2s[tid]   = ((b2[tid] - m2[tid]) * inv2 + be2[tid]) * 0.5f;
    }
    __syncthreads();
    for (int i = tid; i < H * H; i += THREADS) {
        int p = i >> 7, o = i & 127;
        w2h[p * W2_PITCH + o] = __float2half_rn(w2[i] * inv2s[p] * 0.5f);
    }
    __syncthreads();

    // ---- stationary A fragments: warp w covers outchans 16w..16w+15 ----
    unsigned aF[8][4];
    {
        unsigned w2base = smem_u32(w2h);
        int r   = 16 * warp + (lane & 15);
        int ch8 = (lane >> 4) * 8;
#pragma unroll
        for (int kk = 0; kk < 8; kk++)
            ldmA4(aF[kk], w2base + (unsigned)((r * W2_PITCH) + kk * 16 + ch8) * 2u);
    }

    // ---- per-thread build params ----
    const int mych = tid & 127;
    const int ph   = tid >> 7;
    float w1a, w1b, w1c, c1v;
    {
        float inv1 = g1[mych] * rsqrtf(rv1[mych] + 1e-5f);
        w1a = w1[mych * 3 + 0] * inv1;
        w1b = w1[mych * 3 + 1] * inv1;
        w1c = w1[mych * 3 + 2] * inv1;
        c1v = (b1[mych] - m1[mych]) * inv1 + be1[mych];
    }
    const int q  = lane >> 2;
    const int pp = lane & 3;
    const float c2Lo = c2s[16 * warp + q];          // pre-halved
    const float c2Hi = c2s[16 * warp + q + 8];

    const unsigned indbase = smem_u32(smraw + OFF_IND);
    unsigned* indw = reinterpret_cast<unsigned*>(smraw + OFF_IND) + mych * (IND_PITCH / 2);

    // hoisted ldmatrix base addresses (tile-invariant)
    unsigned adb[4];
#pragma unroll
    for (int j2 = 0; j2 < 4; j2++)
        adb[j2] = indbase + (unsigned)((32 * j2 + lane) * IND_PITCH) * 2u;

    // ---- contiguous tile span: block = (batch bb, row span j of 37) ----
    const int bb = blockIdx.x / BLK_PER_B;
    const int j  = blockIdx.x % BLK_PER_B;
    const int r0 = (j * T) / BLK_PER_B;
    const int r1 = ((j + 1) * T) / BLK_PER_B;
    const float* xb = x + (size_t)bb * (T * C * V);

    int cLo = 0, cHi = 0;                    // integer spike counts across all tiles

    for (int r = r0; r < r1; r++) {
        const float4* xr4 = reinterpret_cast<const float4*>(xb + r * (C * V));

        __syncthreads();                     // prior tile's mma reads complete
        // build indicator in 2 chunks of 4 positions (low register pressure)
#pragma unroll
        for (int c = 0; c < 2; c++) {
            float4 v0 = xr4[2 * ph + c];     // x0, positions 8ph+4c..+3
            float4 v1 = xr4[4 + 2 * ph + c]; // x1
            float4 v2 = xr4[8 + 2 * ph + c]; // x2
            const float* f0 = reinterpret_cast<const float*>(&v0);
            const float* f1 = reinterpret_cast<const float*>(&v1);
            const float* f2 = reinterpret_cast<const float*>(&v2);
            unsigned pk0[4], pk1[4];
#pragma unroll
            for (int jj = 0; jj < 4; jj++) {
                float h = fmaf(w1a, f0[jj], fmaf(w1b, f1[jj], fmaf(w1c, f2[jj], c1v)));
                bool s4 = h >= 1.0f;
                bool s3 = h >= TH3;
                bool s2 = h >= TH2p;
                bool s1 = h >= TH1p;
                pk0[jj] = (s4 ? 0x3C00u : 0u) | ((s3 && !s4) ? 0x3C000000u : 0u);        // cat4|cat3
                pk1[jj] = ((s2 && !s3) ? 0x3C00u : 0u) | ((s1 && !s2) ? 0x3C000000u : 0u); // cat2|cat1
            }
            int g = 2 * ph + c;
            *reinterpret_cast<uint4*>(indw + 8 * g)     = make_uint4(pk0[0], pk0[1], pk0[2], pk0[3]);
            *reinterpret_cast<uint4*>(indw + 8 * g + 4) = make_uint4(pk1[0], pk1[1], pk1[2], pk1[3]);
        }
        __syncthreads();

        mma_g(0, adb, aF, c2Lo, c2Hi, cLo, cHi);
        mma_g(1, adb, aF, c2Lo, c2Hi, cLo, cHi);
        mma_g(2, adb, aF, c2Lo, c2Hi, cLo, cHi);
        mma_g(3, adb, aF, c2Lo, c2Hi, cLo, cHi);
    }

    // single flush: reduce positions within quad, one atomic set per block
    cLo += __shfl_xor_sync(FULL, cLo, 1); cLo += __shfl_xor_sync(FULL, cLo, 2);
    cHi += __shfl_xor_sync(FULL, cHi, 1); cHi += __shfl_xor_sync(FULL, cHi, 2);
    if (pp == 0) {                           // exact integer-valued fp32 adds
        atomicAdd(&g_acc[bb * H + 16 * warp + q], (float)cLo);
        atomicAdd(&g_acc[bb * H + 16 * warp + q + 8], (float)cHi);
    }

    // ---- last-block epilogue: feat -> classifier, reset state ----
    __shared__ unsigned s_ticket;
    __threadfence();
    __syncthreads();
    if (tid == 0) s_ticket = atomicAdd(&g_ctr, 1u);
    __syncthreads();
    if (s_ticket == NBLK - 1) {
        __threadfence();
        float* feat = reinterpret_cast<float*>(smraw + OFF_IND);
        for (int i = tid; i < B * H; i += THREADS) {
            float v = __ldcg(&g_acc[i]);
            feat[i] = v * (1.f / (4.f * (float)(T * V)));
            g_acc[i] = 0.f;
        }
        __syncthreads();
        if (tid < B * NC) {
            int b = tid / NC, n = tid % NC;
            float s = bc[n];
#pragma unroll 8
            for (int pch = 0; pch < H; pch++)
                s = fmaf(wc[n * H + pch], feat[b * H + pch], s);
            out[b * NC + n] = s;
        }
        if (tid == 0) atomicExch(&g_ctr, 0u);
    }
}

extern "C" void kernel_launch(void* const* d_in, const int* in_sizes, int n_in,
                              void* d_out, int out_size) {
    const float* x   = (const float*)d_in[0];
    const float* w1  = (const float*)d_in[1];
    const float* b1  = (const float*)d_in[2];
    const float* g1  = (const float*)d_in[3];
    const float* be1 = (const float*)d_in[4];
    const float* m1  = (const float*)d_in[5];
    const float* rv1 = (const float*)d_in[6];
    const float* w2  = (const float*)d_in[7];
    const float* b2  = (const float*)d_in[8];
    const float* g2  = (const float*)d_in[9];
    const float* be2 = (const float*)d_in[10];
    const float* m2  = (const float*)d_in[11];
    const float* rv2 = (const float*)d_in[12];
    const float* wc  = (const float*)d_in[13];
    const float* bc  = (const float*)d_in[14];

    cudaFuncSetAttribute(snn_main, cudaFuncAttributeMaxDynamicSharedMemorySize, SM_BYTES);

    snn_main<<<NBLK, THREADS, SM_BYTES>>>(x, w1, b1, g1, be1, m1, rv1,
                                          w2, b2, g2, be2, m2, rv2,
                                          wc, bc, (float*)d_out);
}